// round 7
// baseline (speedup 1.0000x reference)
#include <cuda_runtime.h>
#include <cuda_bf16.h>
#include <float.h>

#define Bn   4
#define Nn   8192
#define Cc   256
#define Kk   16
#define Ff   512
#define ROWS (Bn*Nn)
#define CAP  160         // append-buffer capacity per query

__device__ float4 g_pos4 [ROWS];   // original order: (x,y,z,|p|^2)
__device__ float4 g_pos4s[ROWS];   // sorted-by-x order
__device__ int    g_sid  [ROWS];   // sorted pos -> original idx (batch-local)
__device__ int    g_ovf  [ROWS];   // overflow flags
__device__ float  g_M[Cc * Ff];
__device__ float  g_Y[(size_t)ROWS * Ff];
__device__ int    g_idx[ROWS * Kk];

// ---------------------------------------------------------------------------
__global__ void prep_pos_kernel(const float* __restrict__ qpos) {
    int i = blockIdx.x * blockDim.x + threadIdx.x;
    if (i >= ROWS) return;
    float x = qpos[i*3+0], y = qpos[i*3+1], z = qpos[i*3+2];
    float n = fmaf(z, z, fmaf(y, y, x * x));
    g_pos4[i] = make_float4(x, y, z, n);
}

__global__ void prep_M_kernel(const float* __restrict__ W) {
    int i = blockIdx.x * blockDim.x + threadIdx.x;
    if (i >= Cc * Ff) return;
    int r = i / Ff;
    int c = i % Ff;
    float v;
    if (c < Cc) v = W[r * Cc + c];
    else        v = W[(Cc + r) * Cc + (c - Cc)] - W[r * Cc + (c - Cc)];
    g_M[i] = v;
}

// ---------------------------------------------------------------------------
// Heuristic spatial sort (scan-order only; KNN stays exact).
// ---------------------------------------------------------------------------
__global__ __launch_bounds__(512) void sort_kernel() {
    const int b   = blockIdx.x;
    const int tid = threadIdx.x;
    __shared__ unsigned sk[Nn];          // 32 KB

    for (int i = tid; i < Nn; i += 512) {
        unsigned u = __float_as_uint(g_pos4[b*Nn + i].x);
        u = (u & 0x80000000u) ? ~u : (u | 0x80000000u);
        sk[i] = (u & 0xFFFFE000u) | (unsigned)i;
    }
    __syncthreads();

    for (int k = 2; k <= Nn; k <<= 1) {
        for (int j = k >> 1; j > 0; j >>= 1) {
            for (int t = tid; t < Nn/2; t += 512) {
                int i   = 2*t - (t & (j - 1));
                int ixj = i + j;
                unsigned a = sk[i], c = sk[ixj];
                bool asc = ((i & k) == 0);
                if ((a > c) == asc) { sk[i] = c; sk[ixj] = a; }
            }
            __syncthreads();
        }
    }

    for (int i = tid; i < Nn; i += 512) {
        int orig = (int)(sk[i] & 8191u);
        g_pos4s[b*Nn + i] = g_pos4[b*Nn + orig];
        g_sid  [b*Nn + i] = orig;
    }
}

// ---------------------------------------------------------------------------
// Fused knn + sgemm mega-kernel. Even blocks run KNN (latency/LDS-bound),
// odd blocks run SGEMM (fma-bound); co-residency overlaps the two pipes.
// ---------------------------------------------------------------------------
struct KnnSm {
    float4 tile[1024];          // 16 KB
    float  ad[32][CAP];         // 20 KB append dists
    int    ai[32][CAP];         // 20 KB append ids (sorted space)
    float  bd[32][Kk];
    int    bi[32][Kk];
    float  sthr[32];
    int    acnt[32];
    int    ovf1[32];
};
struct GemmSm {
    float As[16][128];
    float Bs[16][128];
};
union FusedSm { KnnSm k; GemmSm g; };

__device__ __forceinline__ void knn_block(FusedSm& smu, int kb) {
    KnnSm& S = smu.k;
    const int b    = kb >> 8;                  // 0..3
    const int bxk  = kb & 255;                 // 0..255
    const int tid  = threadIdx.x;
    const int qloc = tid >> 3;                 // 0..31
    const int s    = tid & 7;                  // 0..7
    const int qs   = bxk * 32 + qloc;          // sorted query position

    const float4* __restrict__ pos = g_pos4s + b * Nn;
    const int*    __restrict__ sid = g_sid   + b * Nn;

    float4 me = pos[qs];
    const float qx = me.x, qy = me.y, qz = me.z;

    const int ctile = bxk >> 5;
    int order[8];
    {
        int n = 0;
        order[n++] = ctile;
        for (int d = 1; d < 8; ++d) {
            if (ctile + d < 8)  order[n++] = ctile + d;
            if (ctile - d >= 0) order[n++] = ctile - d;
        }
    }

    // ---- load tile 0 ----
    {
        const int t0 = order[0] * 1024;
#pragma unroll
        for (int j = 0; j < 4; ++j)
            S.tile[tid + j * 256] = pos[t0 + tid + j * 256];
    }
    if (tid < 32) S.acnt[tid] = 0;
    __syncthreads();

    // ---- phase 1: branch-free per-thread top-2 over tile0 sample ----
    float t1 = FLT_MAX, t2 = FLT_MAX;
#pragma unroll 8
    for (int m = 0; m < 128; m += 4) {
        float4 c0 = S.tile[s + (m + 0) * 8];
        float4 c1 = S.tile[s + (m + 1) * 8];
        float4 c2 = S.tile[s + (m + 2) * 8];
        float4 c3 = S.tile[s + (m + 3) * 8];
        float d0 = fmaf(-2.0f, fmaf(qz, c0.z, fmaf(qy, c0.y, qx * c0.x)), c0.w);
        float d1 = fmaf(-2.0f, fmaf(qz, c1.z, fmaf(qy, c1.y, qx * c1.x)), c1.w);
        float d2 = fmaf(-2.0f, fmaf(qz, c2.z, fmaf(qy, c2.y, qx * c2.x)), c2.w);
        float d3 = fmaf(-2.0f, fmaf(qz, c3.z, fmaf(qy, c3.y, qx * c3.x)), c3.w);
        float mn01 = fminf(d0, d1), mx01 = fmaxf(d0, d1);
        float mn23 = fminf(d2, d3), mx23 = fmaxf(d2, d3);
        float s1 = fminf(mn01, mn23);
        float s2 = fminf(fmaxf(mn01, mn23), fminf(mx01, mx23));
        float nt1 = fminf(t1, s1);
        t2 = fminf(fmaxf(t1, s1), fminf(t2, s2));
        t1 = nt1;
    }
    float thrU = t2;
    thrU = fmaxf(thrU, __shfl_xor_sync(0xffffffffu, thrU, 1));
    thrU = fmaxf(thrU, __shfl_xor_sync(0xffffffffu, thrU, 2));
    thrU = fmaxf(thrU, __shfl_xor_sync(0xffffffffu, thrU, 4));

    // ---- phase 1.5: append tile0 candidates <= thrU ----
    {
        const int t0 = order[0] * 1024;
#pragma unroll 4
        for (int m = 0; m < 128; m += 4) {
            float4 c0 = S.tile[s + (m + 0) * 8];
            float4 c1 = S.tile[s + (m + 1) * 8];
            float4 c2 = S.tile[s + (m + 2) * 8];
            float4 c3 = S.tile[s + (m + 3) * 8];
            float d0 = fmaf(-2.0f, fmaf(qz, c0.z, fmaf(qy, c0.y, qx * c0.x)), c0.w);
            float d1 = fmaf(-2.0f, fmaf(qz, c1.z, fmaf(qy, c1.y, qx * c1.x)), c1.w);
            float d2 = fmaf(-2.0f, fmaf(qz, c2.z, fmaf(qy, c2.y, qx * c2.x)), c2.w);
            float d3 = fmaf(-2.0f, fmaf(qz, c3.z, fmaf(qy, c3.y, qx * c3.x)), c3.w);
            float mn = fminf(fminf(d0, d1), fminf(d2, d3));
            if (mn <= thrU) {
                float dv[4] = {d0, d1, d2, d3};
#pragma unroll
                for (int c = 0; c < 4; ++c) {
                    if (dv[c] <= thrU) {
                        int slot = atomicAdd(&S.acnt[qloc], 1);
                        if (slot < CAP) {
                            S.ad[qloc][slot] = dv[c];
                            S.ai[qloc][slot] = t0 + s + (m + c) * 8;
                        }
                    }
                }
            }
        }
    }
    __syncthreads();

    // ---- mid-merge: exact tile0 top-16 with ids -> tight thr0 ----
    if (tid < 32) {
        const int cntRaw = S.acnt[tid];
        const int cnt    = cntRaw < CAP ? cntRaw : CAP;
        float md[Kk]; int mi[Kk];
#pragma unroll
        for (int i = 0; i < Kk; ++i) { md[i] = FLT_MAX; mi[i] = 0; }
        float mthr = FLT_MAX;
        for (int t = 0; t < cnt; ++t) {
            float cd = S.ad[tid][t];
            if (cd < mthr) {
                int ci = S.ai[tid][t];
#pragma unroll
                for (int u = 0; u < Kk; ++u) {
                    bool  sw = cd < md[u];
                    float od = md[u]; int oi = mi[u];
                    md[u] = sw ? cd : od;  mi[u] = sw ? ci : oi;
                    cd    = sw ? od : cd;  ci    = sw ? oi : ci;
                }
                mthr = md[Kk - 1];
            }
        }
#pragma unroll
        for (int i = 0; i < Kk; ++i) { S.bd[tid][i] = md[i]; S.bi[tid][i] = mi[i]; }
        S.sthr[tid] = mthr;
        S.ovf1[tid] = (cntRaw > CAP);
        S.acnt[tid] = 0;
    }

    // ---- phase 2: tiles 1..7, thr0-gated append ----
    for (int ot = 1; ot < 8; ++ot) {
        const int t0 = order[ot] * 1024;
        __syncthreads();
#pragma unroll
        for (int j = 0; j < 4; ++j)
            S.tile[tid + j * 256] = pos[t0 + tid + j * 256];
        __syncthreads();

        const float thr0 = S.sthr[qloc];
#pragma unroll 4
        for (int m = 0; m < 128; m += 4) {
            float4 c0 = S.tile[s + (m + 0) * 8];
            float4 c1 = S.tile[s + (m + 1) * 8];
            float4 c2 = S.tile[s + (m + 2) * 8];
            float4 c3 = S.tile[s + (m + 3) * 8];
            float d0 = fmaf(-2.0f, fmaf(qz, c0.z, fmaf(qy, c0.y, qx * c0.x)), c0.w);
            float d1 = fmaf(-2.0f, fmaf(qz, c1.z, fmaf(qy, c1.y, qx * c1.x)), c1.w);
            float d2 = fmaf(-2.0f, fmaf(qz, c2.z, fmaf(qy, c2.y, qx * c2.x)), c2.w);
            float d3 = fmaf(-2.0f, fmaf(qz, c3.z, fmaf(qy, c3.y, qx * c3.x)), c3.w);
            float mn = fminf(fminf(d0, d1), fminf(d2, d3));
            if (mn <= thr0) {
                float dv[4] = {d0, d1, d2, d3};
#pragma unroll
                for (int c = 0; c < 4; ++c) {
                    if (dv[c] <= thr0) {
                        int slot = atomicAdd(&S.acnt[qloc], 1);
                        if (slot < CAP) {
                            S.ad[qloc][slot] = dv[c];
                            S.ai[qloc][slot] = t0 + s + (m + c) * 8;
                        }
                    }
                }
            }
        }
    }
    __syncthreads();

    // ---- final merge ----
    if (tid < 32) {
        const int cntRaw = S.acnt[tid];
        const int cnt    = cntRaw < CAP ? cntRaw : CAP;
        float md[Kk]; int mi[Kk];
#pragma unroll
        for (int i = 0; i < Kk; ++i) { md[i] = S.bd[tid][i]; mi[i] = S.bi[tid][i]; }
        float mthr = md[Kk - 1];
        for (int t = 0; t < cnt; ++t) {
            float cd = S.ad[tid][t];
            if (cd < mthr) {
                int ci = S.ai[tid][t];
#pragma unroll
                for (int u = 0; u < Kk; ++u) {
                    bool  sw = cd < md[u];
                    float od = md[u]; int oi = mi[u];
                    md[u] = sw ? cd : od;  mi[u] = sw ? ci : oi;
                    cd    = sw ? od : cd;  ci    = sw ? oi : ci;
                }
                mthr = md[Kk - 1];
            }
        }
        const int orig = sid[bxk * 32 + tid];
        const int gq   = b * Nn + orig;
        g_ovf[gq] = (S.ovf1[tid] || cntRaw > CAP) ? 1 : 0;
#pragma unroll
        for (int i = 0; i < Kk; ++i) g_idx[gq * Kk + i] = sid[mi[i]];
    }
}

__device__ __forceinline__ void gemm_block(FusedSm& smu, int sb, const float* __restrict__ A) {
    GemmSm& S = smu.g;
    const int tid  = threadIdx.x;
    const int bm0  = (sb >> 2) * 128;
    const int bn0  = (sb & 3) * 128;

    const int arow = tid >> 2;
    const int acol = (tid & 3) * 4;
    const int brow = tid >> 5;
    const int bcol = (tid & 31) * 4;

    const int tx = tid & 15, ty = tid >> 4;
    const int c0 = tx * 4, c1 = 64 + tx * 4;
    const int r0 = ty * 4, r1 = 64 + ty * 4;

    float acc[8][8];
#pragma unroll
    for (int i = 0; i < 8; ++i)
#pragma unroll
        for (int j = 0; j < 8; ++j) acc[i][j] = 0.0f;

    for (int kt = 0; kt < Cc; kt += 16) {
        float4 a0 = *(const float4*)(A + (size_t)(bm0 + arow)      * Cc + kt + acol);
        float4 a1 = *(const float4*)(A + (size_t)(bm0 + arow + 64) * Cc + kt + acol);
        float4 b0 = *(const float4*)(g_M + (size_t)(kt + brow)     * Ff + bn0 + bcol);
        float4 b1 = *(const float4*)(g_M + (size_t)(kt + brow + 8) * Ff + bn0 + bcol);

        __syncthreads();
        S.As[acol + 0][arow] = a0.x; S.As[acol + 1][arow] = a0.y;
        S.As[acol + 2][arow] = a0.z; S.As[acol + 3][arow] = a0.w;
        S.As[acol + 0][arow + 64] = a1.x; S.As[acol + 1][arow + 64] = a1.y;
        S.As[acol + 2][arow + 64] = a1.z; S.As[acol + 3][arow + 64] = a1.w;
        *(float4*)&S.Bs[brow][bcol]     = b0;
        *(float4*)&S.Bs[brow + 8][bcol] = b1;
        __syncthreads();

#pragma unroll
        for (int kk = 0; kk < 16; ++kk) {
            float4 af0 = *(const float4*)&S.As[kk][r0];
            float4 af1 = *(const float4*)&S.As[kk][r1];
            float4 bf0 = *(const float4*)&S.Bs[kk][c0];
            float4 bf1 = *(const float4*)&S.Bs[kk][c1];
            float ar[8] = {af0.x, af0.y, af0.z, af0.w, af1.x, af1.y, af1.z, af1.w};
            float br[8] = {bf0.x, bf0.y, bf0.z, bf0.w, bf1.x, bf1.y, bf1.z, bf1.w};
#pragma unroll
            for (int i = 0; i < 8; ++i)
#pragma unroll
                for (int j = 0; j < 8; ++j)
                    acc[i][j] = fmaf(ar[i], br[j], acc[i][j]);
        }
    }

#pragma unroll
    for (int i = 0; i < 8; ++i) {
        int row = bm0 + ((i < 4) ? (r0 + i) : (r1 + i - 4));
        float4 v0 = make_float4(acc[i][0], acc[i][1], acc[i][2], acc[i][3]);
        float4 v1 = make_float4(acc[i][4], acc[i][5], acc[i][6], acc[i][7]);
        *(float4*)(g_Y + (size_t)row * Ff + bn0 + c0) = v0;
        *(float4*)(g_Y + (size_t)row * Ff + bn0 + c1) = v1;
    }
}

__global__ __launch_bounds__(256, 2) void fused_kernel(const float* __restrict__ A) {
    __shared__ FusedSm smu;
    if (blockIdx.x & 1) gemm_block(smu, blockIdx.x >> 1, A);
    else                knn_block (smu, blockIdx.x >> 1);
}

// ---------------------------------------------------------------------------
// Exactness backstop: brute-force redo for overflowed queries (expected none).
// ---------------------------------------------------------------------------
__global__ __launch_bounds__(256) void knn_fix_kernel() {
    const int i = blockIdx.x * 256 + threadIdx.x;
    if (i >= ROWS) return;
    if (!g_ovf[i]) return;
    const int b = i >> 13;
    const float4* __restrict__ pos = g_pos4 + b * Nn;
    float4 me = pos[i & 8191];
    const float qx = me.x, qy = me.y, qz = me.z;
    float dist[Kk]; int nid[Kk];
#pragma unroll
    for (int t = 0; t < Kk; ++t) { dist[t] = FLT_MAX; nid[t] = 0; }
    float thr = FLT_MAX;
    for (int j = 0; j < Nn; ++j) {
        float4 cp = pos[j];
        float d2 = fmaf(-2.0f, fmaf(qz, cp.z, fmaf(qy, cp.y, qx * cp.x)), cp.w);
        if (d2 < thr) {
            float cd = d2; int ci = j;
#pragma unroll
            for (int t = 0; t < Kk; ++t) {
                bool  sw = cd < dist[t];
                float od = dist[t]; int oi = nid[t];
                dist[t] = sw ? cd : od;  nid[t] = sw ? ci : oi;
                cd      = sw ? od : cd;  ci     = sw ? oi : ci;
            }
            thr = dist[Kk - 1];
        }
    }
#pragma unroll
    for (int t = 0; t < Kk; ++t) g_idx[i * Kk + t] = nid[t];
}

// ---------------------------------------------------------------------------
__global__ __launch_bounds__(256) void gather_max_kernel(const float* __restrict__ bias,
                                                         float* __restrict__ out) {
    const int row  = blockIdx.x * 8 + (threadIdx.x >> 5);
    const int lane = threadIdx.x & 31;
    const int b    = row >> 13;

    const int* ir = g_idx + row * Kk;
    int myn = ir[lane & (Kk - 1)];

    const float* Ybase = g_Y + (size_t)(b << 13) * Ff;

    float4 m0 = make_float4(-FLT_MAX, -FLT_MAX, -FLT_MAX, -FLT_MAX);
    float4 m1 = m0;

#pragma unroll
    for (int j = 0; j < Kk; ++j) {
        int nb = __shfl_sync(0xffffffffu, myn, j);
        const float4* Pr = (const float4*)(Ybase + (size_t)nb * Ff);
        float4 a = Pr[lane];
        float4 c = Pr[lane + 32];
        m0.x = fmaxf(m0.x, a.x); m0.y = fmaxf(m0.y, a.y);
        m0.z = fmaxf(m0.z, a.z); m0.w = fmaxf(m0.w, a.w);
        m1.x = fmaxf(m1.x, c.x); m1.y = fmaxf(m1.y, c.y);
        m1.z = fmaxf(m1.z, c.z); m1.w = fmaxf(m1.w, c.w);
    }

    const float4* Ur = (const float4*)(g_Y + (size_t)row * Ff + Cc);
    float4 u0 = Ur[lane], u1 = Ur[lane + 32];
    const float4* Br = (const float4*)bias;
    float4 bb0 = Br[lane], bb1 = Br[lane + 32];

    float4 v0, v1;
    v0.x = m0.x + u0.x + bb0.x; v0.y = m0.y + u0.y + bb0.y;
    v0.z = m0.z + u0.z + bb0.z; v0.w = m0.w + u0.w + bb0.w;
    v1.x = m1.x + u1.x + bb1.x; v1.y = m1.y + u1.y + bb1.y;
    v1.z = m1.z + u1.z + bb1.z; v1.w = m1.w + u1.w + bb1.w;

    v0.x = fmaxf(v0.x, 0.2f * v0.x); v0.y = fmaxf(v0.y, 0.2f * v0.y);
    v0.z = fmaxf(v0.z, 0.2f * v0.z); v0.w = fmaxf(v0.w, 0.2f * v0.w);
    v1.x = fmaxf(v1.x, 0.2f * v1.x); v1.y = fmaxf(v1.y, 0.2f * v1.y);
    v1.z = fmaxf(v1.z, 0.2f * v1.z); v1.w = fmaxf(v1.w, 0.2f * v1.w);

    float4* Or = (float4*)(out + (size_t)row * Cc);
    Or[lane]      = v0;
    Or[lane + 32] = v1;
}

// ---------------------------------------------------------------------------
extern "C" void kernel_launch(void* const* d_in, const int* in_sizes, int n_in,
                              void* d_out, int out_size) {
    const float* q    = (const float*)d_in[0];   // [4,8192,256]
    const float* qpos = (const float*)d_in[1];   // [4,8192,3]
    const float* W    = (const float*)d_in[2];   // [512,256]
    const float* bias = (const float*)d_in[3];   // [256]
    float* out = (float*)d_out;
    (void)in_sizes; (void)n_in; (void)out_size;

    prep_pos_kernel<<<(ROWS + 255) / 256, 256>>>(qpos);
    sort_kernel<<<Bn, 512>>>();
    prep_M_kernel<<<(Cc * Ff + 255) / 256, 256>>>(W);
    fused_kernel<<<2048, 256>>>(q);
    knn_fix_kernel<<<ROWS / 256, 256>>>();
    gather_max_kernel<<<ROWS / 8, 256>>>(bias, out);
}

// round 8
// speedup vs baseline: 1.2347x; 1.2347x over previous
#include <cuda_runtime.h>
#include <cuda_bf16.h>
#include <float.h>

#define Bn   4
#define Nn   8192
#define Cc   256
#define Kk   16
#define Ff   512
#define ROWS (Bn*Nn)
#define CAP  128         // append-buffer capacity per query

__device__ float4 g_pos4 [ROWS];   // original order: (x,y,z,|p|^2)
__device__ float4 g_pos4s[ROWS];   // sorted-by-x order
__device__ int    g_sid  [ROWS];   // sorted pos -> original idx (batch-local)
__device__ int    g_ovf  [ROWS];   // overflow flags
__device__ float  g_M[Cc * Ff];
__device__ float  g_Y[(size_t)ROWS * Ff];
__device__ int    g_idx[ROWS * Kk];

// ---------------------------------------------------------------------------
__global__ void prep_pos_kernel(const float* __restrict__ qpos) {
    int i = blockIdx.x * blockDim.x + threadIdx.x;
    if (i >= ROWS) return;
    float x = qpos[i*3+0], y = qpos[i*3+1], z = qpos[i*3+2];
    float n = fmaf(z, z, fmaf(y, y, x * x));
    g_pos4[i] = make_float4(x, y, z, n);
}

__global__ void prep_M_kernel(const float* __restrict__ W) {
    int i = blockIdx.x * blockDim.x + threadIdx.x;
    if (i >= Cc * Ff) return;
    int r = i / Ff;
    int c = i % Ff;
    float v;
    if (c < Cc) v = W[r * Cc + c];
    else        v = W[(Cc + r) * Cc + (c - Cc)] - W[r * Cc + (c - Cc)];
    g_M[i] = v;
}

// ---------------------------------------------------------------------------
// Heuristic spatial sort (scan-order only; KNN stays exact).
// ---------------------------------------------------------------------------
__global__ __launch_bounds__(512) void sort_kernel() {
    const int b   = blockIdx.x;
    const int tid = threadIdx.x;
    __shared__ unsigned sk[Nn];          // 32 KB

    for (int i = tid; i < Nn; i += 512) {
        unsigned u = __float_as_uint(g_pos4[b*Nn + i].x);
        u = (u & 0x80000000u) ? ~u : (u | 0x80000000u);
        sk[i] = (u & 0xFFFFE000u) | (unsigned)i;
    }
    __syncthreads();

    for (int k = 2; k <= Nn; k <<= 1) {
        for (int j = k >> 1; j > 0; j >>= 1) {
            for (int t = tid; t < Nn/2; t += 512) {
                int i   = 2*t - (t & (j - 1));
                int ixj = i + j;
                unsigned a = sk[i], c = sk[ixj];
                bool asc = ((i & k) == 0);
                if ((a > c) == asc) { sk[i] = c; sk[ixj] = a; }
            }
            __syncthreads();
        }
    }

    for (int i = tid; i < Nn; i += 512) {
        int orig = (int)(sk[i] & 8191u);
        g_pos4s[b*Nn + i] = g_pos4[b*Nn + orig];
        g_sid  [b*Nn + i] = orig;
    }
}

// ---------------------------------------------------------------------------
// KNN v3: warp owns 4 queries (registers); lane scans 1/32 of candidates and
// serves all 4 queries per 16B tile load (LDS traffic /4).
// Phase 1: per-lane top-2 over nearest tile -> warp select-16th => tight thr.
// Phase 2: thr-gated (dist,id) append over all 8 tiles. Final small merge.
// ---------------------------------------------------------------------------
__global__ __launch_bounds__(256) void knn_kernel() {
    const int b    = blockIdx.y;
    const int tid  = threadIdx.x;
    const int w    = tid >> 5;                 // warp 0..7
    const int lane = tid & 31;
    const int qb   = blockIdx.x * 32 + w * 4;  // warp's 4 sorted queries

    const float4* __restrict__ pos = g_pos4s + b * Nn;
    const int*    __restrict__ sid = g_sid   + b * Nn;

    __shared__ float4         tile[1024];      // 16 KB
    __shared__ float          ad[32][CAP];     // 16 KB
    __shared__ unsigned short ai[32][CAP];     //  8 KB
    __shared__ int            acnt[32];

    float qx[4], qy[4], qz[4];
#pragma unroll
    for (int i = 0; i < 4; ++i) {
        float4 m = pos[qb + i];
        qx[i] = m.x; qy[i] = m.y; qz[i] = m.z;
    }

    const int ctile = blockIdx.x >> 5;         // nearest slab

    if (tid < 32) acnt[tid] = 0;
    {
        const int t0 = ctile * 1024;
#pragma unroll
        for (int j = 0; j < 4; ++j)
            tile[tid + j * 256] = pos[t0 + tid + j * 256];
    }
    __syncthreads();

    // ---- phase 1: per-lane top-2 per query over the nearest tile ----
    float t1[4], t2[4];
#pragma unroll
    for (int i = 0; i < 4; ++i) { t1[i] = FLT_MAX; t2[i] = FLT_MAX; }

    for (int m = 0; m < 32; m += 4) {
        float4 c0 = tile[lane + (m + 0) * 32];
        float4 c1 = tile[lane + (m + 1) * 32];
        float4 c2 = tile[lane + (m + 2) * 32];
        float4 c3 = tile[lane + (m + 3) * 32];
#pragma unroll
        for (int i = 0; i < 4; ++i) {
            float d0 = fmaf(-2.0f, fmaf(qz[i], c0.z, fmaf(qy[i], c0.y, qx[i] * c0.x)), c0.w);
            float d1 = fmaf(-2.0f, fmaf(qz[i], c1.z, fmaf(qy[i], c1.y, qx[i] * c1.x)), c1.w);
            float d2 = fmaf(-2.0f, fmaf(qz[i], c2.z, fmaf(qy[i], c2.y, qx[i] * c2.x)), c2.w);
            float d3 = fmaf(-2.0f, fmaf(qz[i], c3.z, fmaf(qy[i], c3.y, qx[i] * c3.x)), c3.w);
            float mn01 = fminf(d0, d1), mx01 = fmaxf(d0, d1);
            float mn23 = fminf(d2, d3), mx23 = fmaxf(d2, d3);
            float s1 = fminf(mn01, mn23);
            float s2 = fminf(fmaxf(mn01, mn23), fminf(mx01, mx23));
            float nt1 = fminf(t1[i], s1);
            t2[i] = fminf(fmaxf(t1[i], s1), fminf(t2[i], s2));
            t1[i] = nt1;
        }
    }

    // ---- warp select-16th of the 64-value union (upper bound on true 16th) ----
    float thr[4];
#pragma unroll
    for (int i = 0; i < 4; ++i) {
        float a = t1[i], bb = t2[i];
        float m = FLT_MAX;
        for (int r = 0; r < 16; ++r) {
            float lo = fminf(a, bb);
            m = lo;
            m = fminf(m, __shfl_xor_sync(0xffffffffu, m, 1));
            m = fminf(m, __shfl_xor_sync(0xffffffffu, m, 2));
            m = fminf(m, __shfl_xor_sync(0xffffffffu, m, 4));
            m = fminf(m, __shfl_xor_sync(0xffffffffu, m, 8));
            m = fminf(m, __shfl_xor_sync(0xffffffffu, m, 16));
            unsigned msk = __ballot_sync(0xffffffffu, lo == m);
            int leader = __ffs(msk) - 1;
            if (lane == leader) {
                if (a <= bb) a = FLT_MAX; else bb = FLT_MAX;
            }
        }
        thr[i] = m;   // 16th smallest of union >= query's true 16th in this tile
    }

    // ---- phase 2: thr-gated append over all 8 tiles (ctile first, resident) ----
    for (int ot = 0; ot < 8; ++ot) {
        const int tt = (ctile + ot) & 7;
        const int t0 = tt * 1024;
        if (ot > 0) {
            __syncthreads();
#pragma unroll
            for (int j = 0; j < 4; ++j)
                tile[tid + j * 256] = pos[t0 + tid + j * 256];
            __syncthreads();
        }
        for (int m = 0; m < 32; m += 4) {
            float4 c0 = tile[lane + (m + 0) * 32];
            float4 c1 = tile[lane + (m + 1) * 32];
            float4 c2 = tile[lane + (m + 2) * 32];
            float4 c3 = tile[lane + (m + 3) * 32];
#pragma unroll
            for (int i = 0; i < 4; ++i) {
                float d0 = fmaf(-2.0f, fmaf(qz[i], c0.z, fmaf(qy[i], c0.y, qx[i] * c0.x)), c0.w);
                float d1 = fmaf(-2.0f, fmaf(qz[i], c1.z, fmaf(qy[i], c1.y, qx[i] * c1.x)), c1.w);
                float d2 = fmaf(-2.0f, fmaf(qz[i], c2.z, fmaf(qy[i], c2.y, qx[i] * c2.x)), c2.w);
                float d3 = fmaf(-2.0f, fmaf(qz[i], c3.z, fmaf(qy[i], c3.y, qx[i] * c3.x)), c3.w);
                float mn = fminf(fminf(d0, d1), fminf(d2, d3));
                if (mn <= thr[i]) {
                    const int ql = w * 4 + i;
                    const int jb = t0 + lane + m * 32;
                    if (d0 <= thr[i]) {
                        int sl = atomicAdd(&acnt[ql], 1);
                        if (sl < CAP) { ad[ql][sl] = d0; ai[ql][sl] = (unsigned short)(jb); }
                    }
                    if (d1 <= thr[i]) {
                        int sl = atomicAdd(&acnt[ql], 1);
                        if (sl < CAP) { ad[ql][sl] = d1; ai[ql][sl] = (unsigned short)(jb + 32); }
                    }
                    if (d2 <= thr[i]) {
                        int sl = atomicAdd(&acnt[ql], 1);
                        if (sl < CAP) { ad[ql][sl] = d2; ai[ql][sl] = (unsigned short)(jb + 64); }
                    }
                    if (d3 <= thr[i]) {
                        int sl = atomicAdd(&acnt[ql], 1);
                        if (sl < CAP) { ad[ql][sl] = d3; ai[ql][sl] = (unsigned short)(jb + 96); }
                    }
                }
            }
        }
    }
    __syncthreads();

    // ---- final merge: warp 0, one lane per query, over ~rank(thr) entries ----
    if (tid < 32) {
        const int cntRaw = acnt[tid];
        const int cnt    = cntRaw < CAP ? cntRaw : CAP;
        float md[Kk]; int mi[Kk];
#pragma unroll
        for (int i = 0; i < Kk; ++i) { md[i] = FLT_MAX; mi[i] = 0; }
        float mthr = FLT_MAX;
        for (int t = 0; t < cnt; ++t) {
            float cd = ad[tid][t];
            if (cd < mthr) {
                int ci = ai[tid][t];
#pragma unroll
                for (int u = 0; u < Kk; ++u) {
                    bool  sw = cd < md[u];
                    float od = md[u]; int oi = mi[u];
                    md[u] = sw ? cd : od;  mi[u] = sw ? ci : oi;
                    cd    = sw ? od : cd;  ci    = sw ? oi : ci;
                }
                mthr = md[Kk - 1];
            }
        }
        const int orig = sid[blockIdx.x * 32 + tid];
        const int gq   = b * Nn + orig;
        g_ovf[gq] = (cntRaw > CAP) ? 1 : 0;
#pragma unroll
        for (int i = 0; i < Kk; ++i) g_idx[gq * Kk + i] = sid[mi[i]];
    }
}

// ---------------------------------------------------------------------------
// Exactness backstop: brute-force redo for overflowed queries (expected none).
// ---------------------------------------------------------------------------
__global__ __launch_bounds__(256) void knn_fix_kernel() {
    const int i = blockIdx.x * 256 + threadIdx.x;
    if (i >= ROWS) return;
    if (!g_ovf[i]) return;
    const int b = i >> 13;
    const float4* __restrict__ pos = g_pos4 + b * Nn;
    float4 me = pos[i & 8191];
    const float qx = me.x, qy = me.y, qz = me.z;
    float dist[Kk]; int nid[Kk];
#pragma unroll
    for (int t = 0; t < Kk; ++t) { dist[t] = FLT_MAX; nid[t] = 0; }
    float thr = FLT_MAX;
    for (int j = 0; j < Nn; ++j) {
        float4 cp = pos[j];
        float d2 = fmaf(-2.0f, fmaf(qz, cp.z, fmaf(qy, cp.y, qx * cp.x)), cp.w);
        if (d2 < thr) {
            float cd = d2; int ci = j;
#pragma unroll
            for (int t = 0; t < Kk; ++t) {
                bool  sw = cd < dist[t];
                float od = dist[t]; int oi = nid[t];
                dist[t] = sw ? cd : od;  nid[t] = sw ? ci : oi;
                cd      = sw ? od : cd;  ci     = sw ? oi : ci;
            }
            thr = dist[Kk - 1];
        }
    }
#pragma unroll
    for (int t = 0; t < Kk; ++t) g_idx[i * Kk + t] = nid[t];
}

// ---------------------------------------------------------------------------
__global__ __launch_bounds__(256, 2) void sgemm_kernel(const float* __restrict__ A) {
    __shared__ float As[16][128];
    __shared__ float Bs[16][128];

    const int tid  = threadIdx.x;
    const int bm0  = blockIdx.y * 128;
    const int bn0  = blockIdx.x * 128;

    const int arow = tid >> 2;
    const int acol = (tid & 3) * 4;
    const int brow = tid >> 5;
    const int bcol = (tid & 31) * 4;

    const int tx = tid & 15, ty = tid >> 4;
    const int c0 = tx * 4, c1 = 64 + tx * 4;
    const int r0 = ty * 4, r1 = 64 + ty * 4;

    float acc[8][8];
#pragma unroll
    for (int i = 0; i < 8; ++i)
#pragma unroll
        for (int j = 0; j < 8; ++j) acc[i][j] = 0.0f;

    for (int kt = 0; kt < Cc; kt += 16) {
        float4 a0 = *(const float4*)(A + (size_t)(bm0 + arow)      * Cc + kt + acol);
        float4 a1 = *(const float4*)(A + (size_t)(bm0 + arow + 64) * Cc + kt + acol);
        float4 b0 = *(const float4*)(g_M + (size_t)(kt + brow)     * Ff + bn0 + bcol);
        float4 b1 = *(const float4*)(g_M + (size_t)(kt + brow + 8) * Ff + bn0 + bcol);

        __syncthreads();
        As[acol + 0][arow] = a0.x; As[acol + 1][arow] = a0.y;
        As[acol + 2][arow] = a0.z; As[acol + 3][arow] = a0.w;
        As[acol + 0][arow + 64] = a1.x; As[acol + 1][arow + 64] = a1.y;
        As[acol + 2][arow + 64] = a1.z; As[acol + 3][arow + 64] = a1.w;
        *(float4*)&Bs[brow][bcol]     = b0;
        *(float4*)&Bs[brow + 8][bcol] = b1;
        __syncthreads();

#pragma unroll
        for (int kk = 0; kk < 16; ++kk) {
            float4 af0 = *(const float4*)&As[kk][r0];
            float4 af1 = *(const float4*)&As[kk][r1];
            float4 bf0 = *(const float4*)&Bs[kk][c0];
            float4 bf1 = *(const float4*)&Bs[kk][c1];
            float ar[8] = {af0.x, af0.y, af0.z, af0.w, af1.x, af1.y, af1.z, af1.w};
            float br[8] = {bf0.x, bf0.y, bf0.z, bf0.w, bf1.x, bf1.y, bf1.z, bf1.w};
#pragma unroll
            for (int i = 0; i < 8; ++i)
#pragma unroll
                for (int j = 0; j < 8; ++j)
                    acc[i][j] = fmaf(ar[i], br[j], acc[i][j]);
        }
    }

#pragma unroll
    for (int i = 0; i < 8; ++i) {
        int row = bm0 + ((i < 4) ? (r0 + i) : (r1 + i - 4));
        float4 v0 = make_float4(acc[i][0], acc[i][1], acc[i][2], acc[i][3]);
        float4 v1 = make_float4(acc[i][4], acc[i][5], acc[i][6], acc[i][7]);
        *(float4*)(g_Y + (size_t)row * Ff + bn0 + c0) = v0;
        *(float4*)(g_Y + (size_t)row * Ff + bn0 + c1) = v1;
    }
}

// ---------------------------------------------------------------------------
__global__ __launch_bounds__(256) void gather_max_kernel(const float* __restrict__ bias,
                                                         float* __restrict__ out) {
    const int row  = blockIdx.x * 8 + (threadIdx.x >> 5);
    const int lane = threadIdx.x & 31;
    const int b    = row >> 13;

    const int* ir = g_idx + row * Kk;
    int myn = ir[lane & (Kk - 1)];

    const float* Ybase = g_Y + (size_t)(b << 13) * Ff;

    float4 m0 = make_float4(-FLT_MAX, -FLT_MAX, -FLT_MAX, -FLT_MAX);
    float4 m1 = m0;

#pragma unroll
    for (int j = 0; j < Kk; ++j) {
        int nb = __shfl_sync(0xffffffffu, myn, j);
        const float4* Pr = (const float4*)(Ybase + (size_t)nb * Ff);
        float4 a = Pr[lane];
        float4 c = Pr[lane + 32];
        m0.x = fmaxf(m0.x, a.x); m0.y = fmaxf(m0.y, a.y);
        m0.z = fmaxf(m0.z, a.z); m0.w = fmaxf(m0.w, a.w);
        m1.x = fmaxf(m1.x, c.x); m1.y = fmaxf(m1.y, c.y);
        m1.z = fmaxf(m1.z, c.z); m1.w = fmaxf(m1.w, c.w);
    }

    const float4* Ur = (const float4*)(g_Y + (size_t)row * Ff + Cc);
    float4 u0 = Ur[lane], u1 = Ur[lane + 32];
    const float4* Br = (const float4*)bias;
    float4 bb0 = Br[lane], bb1 = Br[lane + 32];

    float4 v0, v1;
    v0.x = m0.x + u0.x + bb0.x; v0.y = m0.y + u0.y + bb0.y;
    v0.z = m0.z + u0.z + bb0.z; v0.w = m0.w + u0.w + bb0.w;
    v1.x = m1.x + u1.x + bb1.x; v1.y = m1.y + u1.y + bb1.y;
    v1.z = m1.z + u1.z + bb1.z; v1.w = m1.w + u1.w + bb1.w;

    v0.x = fmaxf(v0.x, 0.2f * v0.x); v0.y = fmaxf(v0.y, 0.2f * v0.y);
    v0.z = fmaxf(v0.z, 0.2f * v0.z); v0.w = fmaxf(v0.w, 0.2f * v0.w);
    v1.x = fmaxf(v1.x, 0.2f * v1.x); v1.y = fmaxf(v1.y, 0.2f * v1.y);
    v1.z = fmaxf(v1.z, 0.2f * v1.z); v1.w = fmaxf(v1.w, 0.2f * v1.w);

    float4* Or = (float4*)(out + (size_t)row * Cc);
    Or[lane]      = v0;
    Or[lane + 32] = v1;
}

// ---------------------------------------------------------------------------
extern "C" void kernel_launch(void* const* d_in, const int* in_sizes, int n_in,
                              void* d_out, int out_size) {
    const float* q    = (const float*)d_in[0];   // [4,8192,256]
    const float* qpos = (const float*)d_in[1];   // [4,8192,3]
    const float* W    = (const float*)d_in[2];   // [512,256]
    const float* bias = (const float*)d_in[3];   // [256]
    float* out = (float*)d_out;
    (void)in_sizes; (void)n_in; (void)out_size;

    prep_pos_kernel<<<(ROWS + 255) / 256, 256>>>(qpos);
    sort_kernel<<<Bn, 512>>>();
    prep_M_kernel<<<(Cc * Ff + 255) / 256, 256>>>(W);
    knn_kernel<<<dim3(Nn / 32, Bn), 256>>>();
    knn_fix_kernel<<<ROWS / 256, 256>>>();
    sgemm_kernel<<<dim3(Ff / 128, ROWS / 128), 256>>>(q);
    gather_max_kernel<<<ROWS / 8, 256>>>(bias, out);
}